// round 10
// baseline (speedup 1.0000x reference)
#include <cuda_runtime.h>
#include <cuda_bf16.h>
#include <cstdint>

// GCN: 2x gcn_conv + concat + leaky_relu + linear head.
// GEMMs: bf16x3 split-precision mma.sync + ldmatrix (R7 mainloop).
// R10: GEMM2 split into independent half (overlaps gather1) + dependent half.

#define NMAX 100352
#define EMAX 602112

__device__ __align__(16) float g_h  [(size_t)NMAX * 128];   // h1, then final h2
__device__ __align__(16) float g_h2 [(size_t)NMAX * 128];   // partial: lk(x)@W2_top
__device__ __align__(16) float g_agg[(size_t)NMAX * 128];   // lk(agg1 + b1)
__device__ __align__(16) float g_dinv[NMAX];
__device__ __align__(16) int   g_deg [NMAX];
__device__ __align__(16) int   g_rowptr[NMAX];
__device__ __align__(16) int   g_cursor[NMAX];
__device__ __align__(16) int   g_csrc[EMAX];
__device__ __align__(16) int   g_bsum[1024];
__device__ int g_is64;
#define BSTRIDE 136
#define BSLOTSZ (128 * BSTRIDE)
__device__ __align__(16) unsigned short g_Bhi[3 * BSLOTSZ];
__device__ __align__(16) unsigned short g_Blo[3 * BSLOTSZ];

__device__ __forceinline__ float lk(float v) { return v > 0.f ? v : 0.01f * v; }

__device__ __forceinline__ int edge_at(const int* ei, int is64, size_t idx) {
    if (is64) return (int)((const long long*)ei)[idx];
    return ei[idx];
}

__device__ __forceinline__ void split2(float a, float b, uint32_t& hi, uint32_t& lo) {
    __nv_bfloat16 ha = __float2bfloat16(a), hb = __float2bfloat16(b);
    __nv_bfloat16 la = __float2bfloat16(a - __bfloat162float(ha));
    __nv_bfloat16 lb = __float2bfloat16(b - __bfloat162float(hb));
    __nv_bfloat162 H = __nv_bfloat162(ha, hb), L = __nv_bfloat162(la, lb);
    hi = *(uint32_t*)&H;  lo = *(uint32_t*)&L;
}

__device__ __forceinline__ void mma16816(float* c, const uint32_t* a, const uint32_t* b) {
    asm volatile(
        "mma.sync.aligned.m16n8k16.row.col.f32.bf16.bf16.f32 "
        "{%0,%1,%2,%3}, {%4,%5,%6,%7}, {%8,%9}, {%0,%1,%2,%3};"
        : "+f"(c[0]), "+f"(c[1]), "+f"(c[2]), "+f"(c[3])
        : "r"(a[0]), "r"(a[1]), "r"(a[2]), "r"(a[3]), "r"(b[0]), "r"(b[1]));
}

__device__ __forceinline__ uint32_t smem_u32(const void* p) {
    uint32_t a;
    asm("{ .reg .u64 t; cvta.to.shared.u64 t, %1; cvt.u32.u64 %0, t; }" : "=r"(a) : "l"(p));
    return a;
}

#define LDSM_X4(R, addr) \
    asm volatile("ldmatrix.sync.aligned.m8n8.x4.shared.b16 {%0,%1,%2,%3}, [%4];" \
        : "=r"((R)[0]), "=r"((R)[1]), "=r"((R)[2]), "=r"((R)[3]) : "r"(addr))

// =================== CSR build ===================
__global__ void k_zero_deg(const int* __restrict__ ei, int n) {
    int i = blockIdx.x * blockDim.x + threadIdx.x;
    if (i < n) g_deg[i] = 0;
    if (blockIdx.x == 0 && threadIdx.x == 0) {
        int allz = 1;
        for (int t = 0; t < 64; t++)
            if (ei[2 * t + 1] != 0) { allz = 0; break; }
        g_is64 = allz;
    }
}
__global__ void k_hist(const int* __restrict__ ei, int E) {
    int e = blockIdx.x * blockDim.x + threadIdx.x;
    if (e < E) atomicAdd(&g_deg[edge_at(ei, g_is64, (size_t)E + e)], 1);
}
__global__ void __launch_bounds__(1024) k_scan1(int n) {
    __shared__ int sh[1024];
    int tid = threadIdx.x;
    int i = blockIdx.x * 1024 + tid;
    int v = (i < n) ? g_deg[i] : 0;
    if (i < n) g_dinv[i] = rsqrtf((float)(v + 1));
    sh[tid] = v;  __syncthreads();
    for (int o = 1; o < 1024; o <<= 1) {
        int t = (tid >= o) ? sh[tid - o] : 0;
        __syncthreads(); sh[tid] += t; __syncthreads();
    }
    if (i < n) g_rowptr[i] = sh[tid] - v;
    if (tid == 1023) g_bsum[blockIdx.x] = sh[1023];
}
__global__ void __launch_bounds__(1024) k_scan2(int nb) {
    __shared__ int sh[1024];
    int tid = threadIdx.x;
    int v = (tid < nb) ? g_bsum[tid] : 0;
    sh[tid] = v;  __syncthreads();
    for (int o = 1; o < 1024; o <<= 1) {
        int t = (tid >= o) ? sh[tid - o] : 0;
        __syncthreads(); sh[tid] += t; __syncthreads();
    }
    if (tid < nb) g_bsum[tid] = sh[tid] - v;
}
__global__ void k_scan3(int n) {
    int i = blockIdx.x * blockDim.x + threadIdx.x;
    if (i >= n) return;
    int r = g_rowptr[i] + g_bsum[i >> 10];
    g_rowptr[i] = r;  g_cursor[i] = r;
}
__global__ void k_place(const int* __restrict__ ei, int E) {
    int e = blockIdx.x * blockDim.x + threadIdx.x;
    if (e >= E) return;
    int is64 = g_is64;
    int s = edge_at(ei, is64, e);
    int d = edge_at(ei, is64, (size_t)E + e);
    g_csrc[atomicAdd(&g_cursor[d], 1)] = s;
}

// =================== W pre-split ===================
__global__ void k_prepB(const float* __restrict__ W, int Krows, int slotBase) {
    int idx = blockIdx.x * blockDim.x + threadIdx.x;
    if (idx >= Krows * 128) return;
    int k = idx >> 7, n = idx & 127;
    int slot = slotBase + (k >> 7);
    int kl = k & 127;
    float v = W[(size_t)k * 128 + n];
    __nv_bfloat16 h = __float2bfloat16(v);
    __nv_bfloat16 l = __float2bfloat16(v - __bfloat162float(h));
    size_t off = (size_t)slot * BSLOTSZ + n * BSTRIDE + kl;
    g_Bhi[off] = *(unsigned short*)&h;
    g_Blo[off] = *(unsigned short*)&l;
}

// =================== tensor-core GEMM (single phase, K=128) ===================
// out = A @ B[slot]  (+ g_h2 if addsel)   where A = asel ? g_agg : A0 (lk0 applied)
#define ASTRIDE 136
#define ROWB (ASTRIDE * 2)
#define SM_A_HI 0
#define SM_A_LO (128 * ROWB)
#define SM_B_HI (2 * 128 * ROWB)
#define SM_B_LO (3 * 128 * ROWB)
#define SM_TOTAL (4 * 128 * ROWB)

__global__ void __launch_bounds__(256, 1)
k_tgemm(const float* __restrict__ A0, int asel, int lk0, int bslot, int addsel,
        float* __restrict__ Cout, int M) {
    extern __shared__ char smem[];
    __nv_bfloat16* Ah = (__nv_bfloat16*)(smem + SM_A_HI);
    __nv_bfloat16* Al = (__nv_bfloat16*)(smem + SM_A_LO);
    uint32_t smBase = smem_u32(smem);

    int tid  = threadIdx.x;
    int wid  = tid >> 5;
    int lane = tid & 31;
    int q    = lane & 3;
    int wm   = wid & 3;
    int wn   = wid >> 2;
    int m0   = blockIdx.x * 128;

    int aRow  = (lane & 15);
    int aColX = (lane >> 4) << 4;
    int bRow  = (lane & 7) + ((lane >> 4) << 3);
    int bColX = ((lane >> 3) & 1) << 4;

    const float* A = asel ? g_agg : A0;

    float acc[2][8][4];
#pragma unroll
    for (int i = 0; i < 2; i++)
#pragma unroll
        for (int j = 0; j < 8; j++)
#pragma unroll
            for (int c = 0; c < 4; c++) acc[i][j][c] = 0.f;

    // --- load A tile (128x128 fp32), split hi/lo into padded SMEM ---
    for (int t = tid; t < 2048; t += 256) {
        int row = t >> 4;
        int kc  = (t & 15) << 3;
        int gr  = m0 + row;
        float4 v0 = make_float4(0.f, 0.f, 0.f, 0.f), v1 = v0;
        if (gr < M) {
            v0 = *(const float4*)(A + (size_t)gr * 128 + kc);
            v1 = *(const float4*)(A + (size_t)gr * 128 + kc + 4);
            if (lk0) {
                v0.x = lk(v0.x); v0.y = lk(v0.y); v0.z = lk(v0.z); v0.w = lk(v0.w);
                v1.x = lk(v1.x); v1.y = lk(v1.y); v1.z = lk(v1.z); v1.w = lk(v1.w);
            }
        }
        uint4 hi4, lo4;
        split2(v0.x, v0.y, hi4.x, lo4.x);
        split2(v0.z, v0.w, hi4.y, lo4.y);
        split2(v1.x, v1.y, hi4.z, lo4.z);
        split2(v1.z, v1.w, hi4.w, lo4.w);
        *(uint4*)(Ah + row * ASTRIDE + kc) = hi4;
        *(uint4*)(Al + row * ASTRIDE + kc) = lo4;
    }
    // --- copy pre-split B slot image ---
    {
        const uint4* bh = (const uint4*)(g_Bhi + (size_t)bslot * BSLOTSZ);
        const uint4* bl = (const uint4*)(g_Blo + (size_t)bslot * BSLOTSZ);
        uint4* dh = (uint4*)(smem + SM_B_HI);
        uint4* dl = (uint4*)(smem + SM_B_LO);
        for (int t = tid; t < BSLOTSZ / 8; t += 256) { dh[t] = bh[t]; dl[t] = bl[t]; }
    }
    __syncthreads();

    // --- MMA mainloop: 8 K-steps of 16, ldmatrix fragment loads ---
#pragma unroll
    for (int ks = 0; ks < 8; ks++) {
        int kb = ks * 32;

        uint32_t ahi[2][4], alo[2][4];
#pragma unroll
        for (int mt = 0; mt < 2; mt++) {
            uint32_t ad = smBase + (uint32_t)(wm * 32 + mt * 16 + aRow) * ROWB
                        + kb + aColX;
            LDSM_X4(ahi[mt], ad + SM_A_HI);
            LDSM_X4(alo[mt], ad + SM_A_LO);
        }

        uint32_t bhi[8][2], blo[8][2];
#pragma unroll
        for (int t = 0; t < 4; t++) {
            uint32_t bd = smBase + (uint32_t)(wn * 64 + t * 16 + bRow) * ROWB
                        + kb + bColX;
            uint32_t r[4];
            LDSM_X4(r, bd + SM_B_HI);
            bhi[2 * t][0] = r[0]; bhi[2 * t][1] = r[1];
            bhi[2 * t + 1][0] = r[2]; bhi[2 * t + 1][1] = r[3];
            LDSM_X4(r, bd + SM_B_LO);
            blo[2 * t][0] = r[0]; blo[2 * t][1] = r[1];
            blo[2 * t + 1][0] = r[2]; blo[2 * t + 1][1] = r[3];
        }

#pragma unroll
        for (int nt = 0; nt < 8; nt++)
#pragma unroll
            for (int mt = 0; mt < 2; mt++) {
                mma16816(acc[mt][nt], ahi[mt], bhi[nt]);
                mma16816(acc[mt][nt], ahi[mt], blo[nt]);
                mma16816(acc[mt][nt], alo[mt], bhi[nt]);
            }
    }

    // --- epilogue (+ optional partial from g_h2) ---
    int g = lane >> 2;
#pragma unroll
    for (int mt = 0; mt < 2; mt++) {
        int r0 = m0 + wm * 32 + mt * 16 + g;
#pragma unroll
        for (int nt = 0; nt < 8; nt++) {
            int cc = wn * 64 + nt * 8 + q * 2;
            if (r0 < M) {
                float2 v = make_float2(acc[mt][nt][0], acc[mt][nt][1]);
                if (addsel) {
                    float2 p = *(const float2*)(g_h2 + (size_t)r0 * 128 + cc);
                    v.x += p.x; v.y += p.y;
                }
                *(float2*)(Cout + (size_t)r0 * 128 + cc) = v;
            }
            if (r0 + 8 < M) {
                float2 v = make_float2(acc[mt][nt][2], acc[mt][nt][3]);
                if (addsel) {
                    float2 p = *(const float2*)(g_h2 + (size_t)(r0 + 8) * 128 + cc);
                    v.x += p.x; v.y += p.y;
                }
                *(float2*)(Cout + (size_t)(r0 + 8) * 128 + cc) = v;
            }
        }
    }
}

// =================== aggregation (R7 version) ===================
__global__ void k_gather1(const float* __restrict__ b1, int N) {
    int node = (blockIdx.x * blockDim.x + threadIdx.x) >> 5;
    int lane = threadIdx.x & 31;
    if (node >= N) return;
    int c4 = lane << 2;
    float di = g_dinv[node];
    float4 acc = *(const float4*)(g_h + (size_t)node * 128 + c4);
    float s = di * di;
    acc.x *= s; acc.y *= s; acc.z *= s; acc.w *= s;
    int start = g_rowptr[node], deg = g_deg[node];
    for (int j = 0; j < deg; j++) {
        int src = g_csrc[start + j];
        float nrm = di * g_dinv[src];
        float4 v = *(const float4*)(g_h + (size_t)src * 128 + c4);
        acc.x = fmaf(v.x, nrm, acc.x); acc.y = fmaf(v.y, nrm, acc.y);
        acc.z = fmaf(v.z, nrm, acc.z); acc.w = fmaf(v.w, nrm, acc.w);
    }
    float4 bb = *(const float4*)(b1 + c4);
    acc.x = lk(acc.x + bb.x); acc.y = lk(acc.y + bb.y);
    acc.z = lk(acc.z + bb.z); acc.w = lk(acc.w + bb.w);
    *(float4*)(g_agg + (size_t)node * 128 + c4) = acc;
}

__global__ void k_gather2(const float* __restrict__ b2, const float* __restrict__ Wout,
                          const float* __restrict__ bout, float* __restrict__ out, int N) {
    int node = (blockIdx.x * blockDim.x + threadIdx.x) >> 5;
    int lane = threadIdx.x & 31;
    if (node >= N) return;
    int c4 = lane << 2;
    float di = g_dinv[node];
    float4 acc = *(const float4*)(g_h + (size_t)node * 128 + c4);
    float s = di * di;
    acc.x *= s; acc.y *= s; acc.z *= s; acc.w *= s;
    int start = g_rowptr[node], deg = g_deg[node];
    for (int j = 0; j < deg; j++) {
        int src = g_csrc[start + j];
        float nrm = di * g_dinv[src];
        float4 v = *(const float4*)(g_h + (size_t)src * 128 + c4);
        acc.x = fmaf(v.x, nrm, acc.x); acc.y = fmaf(v.y, nrm, acc.y);
        acc.z = fmaf(v.z, nrm, acc.z); acc.w = fmaf(v.w, nrm, acc.w);
    }
    float4 bb = *(const float4*)(b2 + c4);
    float4 ww = *(const float4*)(Wout + c4);
    float r = lk(acc.x + bb.x) * ww.x + lk(acc.y + bb.y) * ww.y +
              lk(acc.z + bb.z) * ww.z + lk(acc.w + bb.w) * ww.w;
#pragma unroll
    for (int o = 16; o; o >>= 1) r += __shfl_xor_sync(0xFFFFFFFFu, r, o);
    if (lane == 0) out[node] = r + bout[0];
}

// =================== launch (stream-parallel DAG) ===================
extern "C" void kernel_launch(void* const* d_in, const int* in_sizes, int n_in,
                              void* d_out, int out_size) {
    const float* x    = (const float*)d_in[0];
    const int*   ei   = (const int*)d_in[1];
    const float* W1   = (const float*)d_in[2];
    const float* b1   = (const float*)d_in[3];
    const float* W2   = (const float*)d_in[4];
    const float* b2   = (const float*)d_in[5];
    const float* Wout = (const float*)d_in[6];
    const float* bout = (const float*)d_in[7];
    float*       out  = (float*)d_out;

    int N = in_sizes[0] / 128;
    int E = in_sizes[1] / 2;

    cudaFuncSetAttribute(k_tgemm, cudaFuncAttributeMaxDynamicSharedMemorySize, SM_TOTAL);

    float *hPtr, *h2Ptr;
    cudaGetSymbolAddress((void**)&hPtr,  g_h);
    cudaGetSymbolAddress((void**)&h2Ptr, g_h2);

    // host-side resources; kernel_launch runs only a few times.
    cudaStream_t s1;
    cudaEvent_t evFork, evCSR, evPrep2, evG2a;
    cudaStreamCreateWithFlags(&s1, cudaStreamNonBlocking);
    cudaEventCreateWithFlags(&evFork, cudaEventDisableTiming);
    cudaEventCreateWithFlags(&evCSR,  cudaEventDisableTiming);
    cudaEventCreateWithFlags(&evPrep2, cudaEventDisableTiming);
    cudaEventCreateWithFlags(&evG2a,  cudaEventDisableTiming);

    const int T = 256;
    int gN = (N + T - 1) / T;
    int gE = (E + T - 1) / T;
    int gW = (N * 32 + T - 1) / T;
    int gM = (N + 127) / 128;
    int nb = (N + 1023) / 1024;

    // fork
    cudaEventRecord(evFork, 0);
    cudaStreamWaitEvent(s1, evFork, 0);

    // --- s1: CSR build + norms, then GEMM2a (independent of gather1) ---
    k_zero_deg<<<gN, T, 0, s1>>>(ei, N);
    k_hist<<<gE, T, 0, s1>>>(ei, E);
    k_scan1<<<nb, 1024, 0, s1>>>(N);
    k_scan2<<<1, 1024, 0, s1>>>(nb);
    k_scan3<<<gN, T, 0, s1>>>(N);
    k_place<<<gE, T, 0, s1>>>(ei, E);
    cudaEventRecord(evCSR, s1);

    // --- stream 0: weights + GEMM1 ---
    k_prepB<<<(128 * 128 + T - 1) / T, T>>>(W1, 128, 0);
    k_prepB<<<(256 * 128 + T - 1) / T, T>>>(W2, 256, 1);
    cudaEventRecord(evPrep2, 0);
    k_tgemm<<<gM, T, SM_TOTAL>>>(x, 0, 0, 0, 0, hPtr, N);      // h1 = x@W1

    // --- s1: GEMM2a = lk(x)@W2_top -> g_h2 (overlaps gather1 on s0) ---
    cudaStreamWaitEvent(s1, evPrep2, 0);
    k_tgemm<<<gM, T, SM_TOTAL, s1>>>(x, 0, 1, 1, 0, h2Ptr, N);
    cudaEventRecord(evG2a, s1);

    // --- stream 0: gather1 (needs CSR + h1) ---
    cudaStreamWaitEvent(0, evCSR, 0);
    k_gather1<<<gW, T>>>(b1, N);

    // GEMM2b = agg1@W2_bot + g_h2 -> g_h
    cudaStreamWaitEvent(0, evG2a, 0);
    k_tgemm<<<gM, T, SM_TOTAL>>>(x, 1, 0, 2, 1, hPtr, N);

    // head
    k_gather2<<<gW, T>>>(b2, Wout, bout, out, N);
}

// round 11
// speedup vs baseline: 1.5808x; 1.5808x over previous
#include <cuda_runtime.h>
#include <cuda_bf16.h>
#include <cstdint>

// GCN: 2x gcn_conv + concat + leaky_relu + linear head.
// GEMMs: bf16x3 split-precision mma.sync + ldmatrix.
// R11: R9 schedule; GEMM SMEM 136KB->104KB (B staged in K=64 chunks) => 2 CTA/SM.

#define NMAX 100352
#define EMAX 602112

__device__ __align__(16) float g_h  [(size_t)NMAX * 128];
__device__ __align__(16) float g_agg[(size_t)NMAX * 128];
__device__ __align__(16) float g_dinv[NMAX];
__device__ __align__(16) int   g_deg [NMAX];
__device__ __align__(16) int   g_rowptr[NMAX];
__device__ __align__(16) int   g_cursor[NMAX];
__device__ __align__(16) int   g_csrc[EMAX];
__device__ __align__(16) int   g_bsum[1024];
__device__ int g_is64;
#define BSTRIDE 136
#define BSLOTSZ (128 * BSTRIDE)
__device__ __align__(16) unsigned short g_Bhi[3 * BSLOTSZ];
__device__ __align__(16) unsigned short g_Blo[3 * BSLOTSZ];

__device__ __forceinline__ float lk(float v) { return v > 0.f ? v : 0.01f * v; }

__device__ __forceinline__ int edge_at(const int* ei, int is64, size_t idx) {
    if (is64) return (int)((const long long*)ei)[idx];
    return ei[idx];
}

__device__ __forceinline__ void split2(float a, float b, uint32_t& hi, uint32_t& lo) {
    __nv_bfloat16 ha = __float2bfloat16(a), hb = __float2bfloat16(b);
    __nv_bfloat16 la = __float2bfloat16(a - __bfloat162float(ha));
    __nv_bfloat16 lb = __float2bfloat16(b - __bfloat162float(hb));
    __nv_bfloat162 H = __nv_bfloat162(ha, hb), L = __nv_bfloat162(la, lb);
    hi = *(uint32_t*)&H;  lo = *(uint32_t*)&L;
}

__device__ __forceinline__ void mma16816(float* c, const uint32_t* a, const uint32_t* b) {
    asm volatile(
        "mma.sync.aligned.m16n8k16.row.col.f32.bf16.bf16.f32 "
        "{%0,%1,%2,%3}, {%4,%5,%6,%7}, {%8,%9}, {%0,%1,%2,%3};"
        : "+f"(c[0]), "+f"(c[1]), "+f"(c[2]), "+f"(c[3])
        : "r"(a[0]), "r"(a[1]), "r"(a[2]), "r"(a[3]), "r"(b[0]), "r"(b[1]));
}

__device__ __forceinline__ uint32_t smem_u32(const void* p) {
    uint32_t a;
    asm("{ .reg .u64 t; cvta.to.shared.u64 t, %1; cvt.u32.u64 %0, t; }" : "=r"(a) : "l"(p));
    return a;
}

#define LDSM_X4(R, addr) \
    asm volatile("ldmatrix.sync.aligned.m8n8.x4.shared.b16 {%0,%1,%2,%3}, [%4];" \
        : "=r"((R)[0]), "=r"((R)[1]), "=r"((R)[2]), "=r"((R)[3]) : "r"(addr))

// =================== CSR build ===================
__global__ void k_zero_deg(const int* __restrict__ ei, int n) {
    int i = blockIdx.x * blockDim.x + threadIdx.x;
    if (i < n) g_deg[i] = 0;
    if (blockIdx.x == 0 && threadIdx.x == 0) {
        int allz = 1;
        for (int t = 0; t < 64; t++)
            if (ei[2 * t + 1] != 0) { allz = 0; break; }
        g_is64 = allz;
    }
}
__global__ void k_hist(const int* __restrict__ ei, int E) {
    int e = blockIdx.x * blockDim.x + threadIdx.x;
    if (e < E) atomicAdd(&g_deg[edge_at(ei, g_is64, (size_t)E + e)], 1);
}
__global__ void __launch_bounds__(1024) k_scan1(int n) {
    __shared__ int sh[1024];
    int tid = threadIdx.x;
    int i = blockIdx.x * 1024 + tid;
    int v = (i < n) ? g_deg[i] : 0;
    if (i < n) g_dinv[i] = rsqrtf((float)(v + 1));
    sh[tid] = v;  __syncthreads();
    for (int o = 1; o < 1024; o <<= 1) {
        int t = (tid >= o) ? sh[tid - o] : 0;
        __syncthreads(); sh[tid] += t; __syncthreads();
    }
    if (i < n) g_rowptr[i] = sh[tid] - v;
    if (tid == 1023) g_bsum[blockIdx.x] = sh[1023];
}
__global__ void __launch_bounds__(1024) k_scan2(int nb) {
    __shared__ int sh[1024];
    int tid = threadIdx.x;
    int v = (tid < nb) ? g_bsum[tid] : 0;
    sh[tid] = v;  __syncthreads();
    for (int o = 1; o < 1024; o <<= 1) {
        int t = (tid >= o) ? sh[tid - o] : 0;
        __syncthreads(); sh[tid] += t; __syncthreads();
    }
    if (tid < nb) g_bsum[tid] = sh[tid] - v;
}
__global__ void k_scan3(int n) {
    int i = blockIdx.x * blockDim.x + threadIdx.x;
    if (i >= n) return;
    int r = g_rowptr[i] + g_bsum[i >> 10];
    g_rowptr[i] = r;  g_cursor[i] = r;
}
__global__ void k_place(const int* __restrict__ ei, int E) {
    int e = blockIdx.x * blockDim.x + threadIdx.x;
    if (e >= E) return;
    int is64 = g_is64;
    int s = edge_at(ei, is64, e);
    int d = edge_at(ei, is64, (size_t)E + e);
    g_csrc[atomicAdd(&g_cursor[d], 1)] = s;
}

// =================== W pre-split ===================
__global__ void k_prepB(const float* __restrict__ W, int Krows, int slotBase) {
    int idx = blockIdx.x * blockDim.x + threadIdx.x;
    if (idx >= Krows * 128) return;
    int k = idx >> 7, n = idx & 127;
    int slot = slotBase + (k >> 7);
    int kl = k & 127;
    float v = W[(size_t)k * 128 + n];
    __nv_bfloat16 h = __float2bfloat16(v);
    __nv_bfloat16 l = __float2bfloat16(v - __bfloat162float(h));
    size_t off = (size_t)slot * BSLOTSZ + n * BSTRIDE + kl;
    g_Bhi[off] = *(unsigned short*)&h;
    g_Blo[off] = *(unsigned short*)&l;
}

// =================== tensor-core GEMM (2 CTA/SM, B chunked BK=64) ===================
#define ASTRIDE 136
#define ROWB (ASTRIDE * 2)                 // 272 B per A row
#define BCH_STRIDE 72
#define BCH_ROWB (BCH_STRIDE * 2)          // 144 B per B chunk row
#define SM_A_HI 0
#define SM_A_LO (128 * ROWB)                       // 34816
#define SM_B_HI (2 * 128 * ROWB)                   // 69632
#define SM_B_LO (2 * 128 * ROWB + 128 * BCH_ROWB)  // 88064
#define SM_TOTAL (2 * 128 * ROWB + 2 * 128 * BCH_ROWB)  // 106496

__global__ void __launch_bounds__(256, 2)
k_tgemm(const float* __restrict__ A0, int lk0, int nphase, int bslot, int M) {
    extern __shared__ char smem[];
    __nv_bfloat16* Ah = (__nv_bfloat16*)(smem + SM_A_HI);
    __nv_bfloat16* Al = (__nv_bfloat16*)(smem + SM_A_LO);
    uint32_t smBase = smem_u32(smem);

    int tid  = threadIdx.x;
    int wid  = tid >> 5;
    int lane = tid & 31;
    int q    = lane & 3;
    int wm   = wid & 3;
    int wn   = wid >> 2;
    int m0   = blockIdx.x * 128;

    int aRow  = (lane & 15);
    int aColX = (lane >> 4) << 4;
    int bRow  = (lane & 7) + ((lane >> 4) << 3);
    int bColX = ((lane >> 3) & 1) << 4;

    float acc[2][8][4];
#pragma unroll
    for (int i = 0; i < 2; i++)
#pragma unroll
        for (int j = 0; j < 8; j++)
#pragma unroll
            for (int c = 0; c < 4; c++) acc[i][j][c] = 0.f;

    for (int phase = 0; phase < nphase; phase++) {
        const float* A = phase ? g_agg : A0;
        int applyLk = phase ? 0 : lk0;
        int slot = bslot + phase;

        if (phase) __syncthreads();

        // --- load A tile (128x128 fp32), split hi/lo into padded SMEM ---
        for (int t = tid; t < 2048; t += 256) {
            int row = t >> 4;
            int kc  = (t & 15) << 3;
            int gr  = m0 + row;
            float4 v0 = make_float4(0.f, 0.f, 0.f, 0.f), v1 = v0;
            if (gr < M) {
                v0 = *(const float4*)(A + (size_t)gr * 128 + kc);
                v1 = *(const float4*)(A + (size_t)gr * 128 + kc + 4);
                if (applyLk) {
                    v0.x = lk(v0.x); v0.y = lk(v0.y); v0.z = lk(v0.z); v0.w = lk(v0.w);
                    v1.x = lk(v1.x); v1.y = lk(v1.y); v1.z = lk(v1.z); v1.w = lk(v1.w);
                }
            }
            uint4 hi4, lo4;
            split2(v0.x, v0.y, hi4.x, lo4.x);
            split2(v0.z, v0.w, hi4.y, lo4.y);
            split2(v1.x, v1.y, hi4.z, lo4.z);
            split2(v1.z, v1.w, hi4.w, lo4.w);
            *(uint4*)(Ah + row * ASTRIDE + kc) = hi4;
            *(uint4*)(Al + row * ASTRIDE + kc) = lo4;
        }

        // --- two K=64 chunks of B ---
        for (int ch = 0; ch < 2; ch++) {
            if (ch) __syncthreads();   // previous chunk's B reads complete

            // copy B chunk: 128 rows x 64 shorts per half (8 uint4/row)
            {
                const uint4* sh_ = (const uint4*)(g_Bhi + (size_t)slot * BSLOTSZ);
                const uint4* sl_ = (const uint4*)(g_Blo + (size_t)slot * BSLOTSZ);
                uint4* dh = (uint4*)(smem + SM_B_HI);
                uint4* dl = (uint4*)(smem + SM_B_LO);
                for (int t = tid; t < 2048; t += 256) {
                    int half = t >> 10;          // 0=hi, 1=lo
                    int r = (t >> 3) & 127;
                    int c = t & 7;
                    int srcIdx = r * 17 + ch * 8 + c;   // 272B rows: 17 uint4
                    int dstIdx = r * 9 + c;             // 144B rows: 9 uint4
                    if (half == 0) dh[dstIdx] = sh_[srcIdx];
                    else           dl[dstIdx] = sl_[srcIdx];
                }
            }
            __syncthreads();

            // --- MMA: 4 K-steps of 16 within this chunk ---
#pragma unroll
            for (int ks = 0; ks < 4; ks++) {
                int kbA = ch * 128 + ks * 32;   // byte offset in A row
                int kbB = ks * 32;              // byte offset in B chunk row

                uint32_t ahi[2][4], alo[2][4];
#pragma unroll
                for (int mt = 0; mt < 2; mt++) {
                    uint32_t ad = smBase + (uint32_t)(wm * 32 + mt * 16 + aRow) * ROWB
                                + kbA + aColX;
                    LDSM_X4(ahi[mt], ad + SM_A_HI);
                    LDSM_X4(alo[mt], ad + SM_A_LO);
                }

                uint32_t bhi[8][2], blo[8][2];
#pragma unroll
                for (int t = 0; t < 4; t++) {
                    uint32_t bd = smBase + (uint32_t)(wn * 64 + t * 16 + bRow) * BCH_ROWB
                                + kbB + bColX;
                    uint32_t r[4];
                    LDSM_X4(r, bd + SM_B_HI);
                    bhi[2 * t][0] = r[0]; bhi[2 * t][1] = r[1];
                    bhi[2 * t + 1][0] = r[2]; bhi[2 * t + 1][1] = r[3];
                    LDSM_X4(r, bd + SM_B_LO);
                    blo[2 * t][0] = r[0]; blo[2 * t][1] = r[1];
                    blo[2 * t + 1][0] = r[2]; blo[2 * t + 1][1] = r[3];
                }

#pragma unroll
                for (int nt = 0; nt < 8; nt++)
#pragma unroll
                    for (int mt = 0; mt < 2; mt++) {
                        mma16816(acc[mt][nt], ahi[mt], bhi[nt]);
                        mma16816(acc[mt][nt], ahi[mt], blo[nt]);
                        mma16816(acc[mt][nt], alo[mt], bhi[nt]);
                    }
            }
        }
    }

    int g = lane >> 2;
#pragma unroll
    for (int mt = 0; mt < 2; mt++) {
        int r0 = m0 + wm * 32 + mt * 16 + g;
#pragma unroll
        for (int nt = 0; nt < 8; nt++) {
            int cc = wn * 64 + nt * 8 + q * 2;
            if (r0 < M)
                *(float2*)(g_h + (size_t)r0 * 128 + cc) =
                    make_float2(acc[mt][nt][0], acc[mt][nt][1]);
            if (r0 + 8 < M)
                *(float2*)(g_h + (size_t)(r0 + 8) * 128 + cc) =
                    make_float2(acc[mt][nt][2], acc[mt][nt][3]);
        }
    }
}

// =================== aggregation (R7 version) ===================
__global__ void k_gather1(const float* __restrict__ b1, int N) {
    int node = (blockIdx.x * blockDim.x + threadIdx.x) >> 5;
    int lane = threadIdx.x & 31;
    if (node >= N) return;
    int c4 = lane << 2;
    float di = g_dinv[node];
    float4 acc = *(const float4*)(g_h + (size_t)node * 128 + c4);
    float s = di * di;
    acc.x *= s; acc.y *= s; acc.z *= s; acc.w *= s;
    int start = g_rowptr[node], deg = g_deg[node];
    for (int j = 0; j < deg; j++) {
        int src = g_csrc[start + j];
        float nrm = di * g_dinv[src];
        float4 v = *(const float4*)(g_h + (size_t)src * 128 + c4);
        acc.x = fmaf(v.x, nrm, acc.x); acc.y = fmaf(v.y, nrm, acc.y);
        acc.z = fmaf(v.z, nrm, acc.z); acc.w = fmaf(v.w, nrm, acc.w);
    }
    float4 bb = *(const float4*)(b1 + c4);
    acc.x = lk(acc.x + bb.x); acc.y = lk(acc.y + bb.y);
    acc.z = lk(acc.z + bb.z); acc.w = lk(acc.w + bb.w);
    *(float4*)(g_agg + (size_t)node * 128 + c4) = acc;
}

__global__ void k_gather2(const float* __restrict__ b2, const float* __restrict__ Wout,
                          const float* __restrict__ bout, float* __restrict__ out, int N) {
    int node = (blockIdx.x * blockDim.x + threadIdx.x) >> 5;
    int lane = threadIdx.x & 31;
    if (node >= N) return;
    int c4 = lane << 2;
    float di = g_dinv[node];
    float4 acc = *(const float4*)(g_h + (size_t)node * 128 + c4);
    float s = di * di;
    acc.x *= s; acc.y *= s; acc.z *= s; acc.w *= s;
    int start = g_rowptr[node], deg = g_deg[node];
    for (int j = 0; j < deg; j++) {
        int src = g_csrc[start + j];
        float nrm = di * g_dinv[src];
        float4 v = *(const float4*)(g_h + (size_t)src * 128 + c4);
        acc.x = fmaf(v.x, nrm, acc.x); acc.y = fmaf(v.y, nrm, acc.y);
        acc.z = fmaf(v.z, nrm, acc.z); acc.w = fmaf(v.w, nrm, acc.w);
    }
    float4 bb = *(const float4*)(b2 + c4);
    float4 ww = *(const float4*)(Wout + c4);
    float r = lk(acc.x + bb.x) * ww.x + lk(acc.y + bb.y) * ww.y +
              lk(acc.z + bb.z) * ww.z + lk(acc.w + bb.w) * ww.w;
#pragma unroll
    for (int o = 16; o; o >>= 1) r += __shfl_xor_sync(0xFFFFFFFFu, r, o);
    if (lane == 0) out[node] = r + bout[0];
}

// =================== launch (R9 stream-parallel DAG) ===================
extern "C" void kernel_launch(void* const* d_in, const int* in_sizes, int n_in,
                              void* d_out, int out_size) {
    const float* x    = (const float*)d_in[0];
    const int*   ei   = (const int*)d_in[1];
    const float* W1   = (const float*)d_in[2];
    const float* b1   = (const float*)d_in[3];
    const float* W2   = (const float*)d_in[4];
    const float* b2   = (const float*)d_in[5];
    const float* Wout = (const float*)d_in[6];
    const float* bout = (const float*)d_in[7];
    float*       out  = (float*)d_out;

    int N = in_sizes[0] / 128;
    int E = in_sizes[1] / 2;

    cudaFuncSetAttribute(k_tgemm, cudaFuncAttributeMaxDynamicSharedMemorySize, SM_TOTAL);

    cudaStream_t s1;
    cudaEvent_t evFork, evCSR;
    cudaStreamCreateWithFlags(&s1, cudaStreamNonBlocking);
    cudaEventCreateWithFlags(&evFork, cudaEventDisableTiming);
    cudaEventCreateWithFlags(&evCSR,  cudaEventDisableTiming);

    const int T = 256;
    int gN = (N + T - 1) / T;
    int gE = (E + T - 1) / T;
    int gW = (N * 32 + T - 1) / T;
    int gM = (N + 127) / 128;
    int nb = (N + 1023) / 1024;

    cudaEventRecord(evFork, 0);
    cudaStreamWaitEvent(s1, evFork, 0);

    // --- s1: CSR build + norms ---
    k_zero_deg<<<gN, T, 0, s1>>>(ei, N);
    k_hist<<<gE, T, 0, s1>>>(ei, E);
    k_scan1<<<nb, 1024, 0, s1>>>(N);
    k_scan2<<<1, 1024, 0, s1>>>(nb);
    k_scan3<<<gN, T, 0, s1>>>(N);
    k_place<<<gE, T, 0, s1>>>(ei, E);
    cudaEventRecord(evCSR, s1);

    // --- stream 0: layer-1 GEMM path ---
    k_prepB<<<(128 * 128 + T - 1) / T, T>>>(W1, 128, 0);
    k_tgemm<<<gM, T, SM_TOTAL>>>(x, 0, 1, 0, N);
    k_prepB<<<(256 * 128 + T - 1) / T, T>>>(W2, 256, 1);   // needed only by GEMM2

    // join: gather1 needs CSR + h1
    cudaStreamWaitEvent(0, evCSR, 0);
    k_gather1<<<gW, T>>>(b1, N);

    // layer 2 + head
    k_tgemm<<<gM, T, SM_TOTAL>>>(x, 1, 2, 1, N);
    k_gather2<<<gW, T>>>(b2, Wout, bout, out, N);
}